// round 1
// baseline (speedup 1.0000x reference)
#include <cuda_runtime.h>
#include <math.h>

// Problem constants (fixed shapes from setup_inputs)
#define T_DIM 1024
#define B_DIM 8
#define C_DIM 1024
#define F_DIM 4096
#define H_DIM 16
#define K_TAPS 15
#define M_DIM (T_DIM * B_DIM)   // 8192 rows
#define NPAD 256                 // H*K=240 padded to 256
#define LN_EPS 1e-5f

// -------- scratch (device globals; no allocation allowed) --------
__device__ float g_wpad[C_DIM * NPAD];              // padded w_lin   (1 MB)
__device__ float g_wraw[M_DIM * NPAD];              // conv logits    (8 MB)
__device__ float g_y[M_DIM * C_DIM];                // post-LN act    (32 MB)
__device__ float g_h[(size_t)M_DIM * F_DIM];        // fc1 output     (128 MB)

// ================= pad w_lin (1024x240 -> 1024x256, zero fill) =================
__global__ void pad_wlin_kernel(const float* __restrict__ wlin, float* __restrict__ out) {
    int i = blockIdx.x * blockDim.x + threadIdx.x;   // over C_DIM*NPAD
    int c = i >> 8;
    int j = i & 255;
    out[i] = (j < H_DIM * K_TAPS) ? wlin[c * (H_DIM * K_TAPS) + j] : 0.0f;
}

// ================= tiled fp32 SGEMM =================
// C[M,N] = A[M,K] @ B[K,N] (+bias) (+relu | +residual)
// BM=BN=128, BK=16, TM=TN=8, 256 threads.
// EPI: 0 = plain, 1 = bias+ReLU, 2 = bias+residual add
constexpr int BM = 128, BN = 128, BK = 16, TM = 8, TN = 8;

template <int EPI>
__global__ __launch_bounds__(256)
void sgemm_kernel(int M, int N, int Kd,
                  const float* __restrict__ A, const float* __restrict__ B,
                  const float* __restrict__ bias, const float* __restrict__ res,
                  float* __restrict__ C) {
    __shared__ float As[BK * BM];   // transposed: As[k][m]
    __shared__ float Bs[BK * BN];

    const int cRow = blockIdx.y;
    const int cCol = blockIdx.x;
    const int tid  = threadIdx.x;

    const int threadCol = tid % (BN / TN);   // 0..15
    const int threadRow = tid / (BN / TN);   // 0..15

    A += (size_t)cRow * BM * Kd;
    B += (size_t)cCol * BN;

    const int innerRowA = tid / (BK / 4);    // 0..63
    const int innerColA = tid % (BK / 4);    // 0..3
    const int innerRowB = tid / (BN / 4);    // 0..7
    const int innerColB = tid % (BN / 4);    // 0..31

    float acc[TM][TN] = {};
    float regM[TM], regN[TN];

    for (int k0 = 0; k0 < Kd; k0 += BK) {
        // load A tile (128x16), store transposed into As[k][m]
        #pragma unroll
        for (int p = 0; p < BM; p += 64) {
            float4 v = *reinterpret_cast<const float4*>(
                &A[(size_t)(innerRowA + p) * Kd + innerColA * 4]);
            As[(innerColA * 4 + 0) * BM + innerRowA + p] = v.x;
            As[(innerColA * 4 + 1) * BM + innerRowA + p] = v.y;
            As[(innerColA * 4 + 2) * BM + innerRowA + p] = v.z;
            As[(innerColA * 4 + 3) * BM + innerRowA + p] = v.w;
        }
        // load B tile (16x128)
        #pragma unroll
        for (int p = 0; p < BK; p += 8) {
            *reinterpret_cast<float4*>(&Bs[(innerRowB + p) * BN + innerColB * 4]) =
                *reinterpret_cast<const float4*>(
                    &B[(size_t)(innerRowB + p) * N + innerColB * 4]);
        }
        __syncthreads();
        A += BK;
        B += (size_t)BK * N;

        #pragma unroll
        for (int k = 0; k < BK; k++) {
            #pragma unroll
            for (int i = 0; i < TM; i++) regM[i] = As[k * BM + threadRow * TM + i];
            #pragma unroll
            for (int j = 0; j < TN; j++) regN[j] = Bs[k * BN + threadCol * TN + j];
            #pragma unroll
            for (int i = 0; i < TM; i++)
                #pragma unroll
                for (int j = 0; j < TN; j++)
                    acc[i][j] += regM[i] * regN[j];
        }
        __syncthreads();
    }

    const int rowBase = cRow * BM + threadRow * TM;
    const int colBase = cCol * BN + threadCol * TN;
    #pragma unroll
    for (int i = 0; i < TM; i++) {
        const int r = rowBase + i;
        #pragma unroll
        for (int j = 0; j < TN; j += 4) {
            const int cidx = colBase + j;
            float4 v = make_float4(acc[i][j], acc[i][j + 1], acc[i][j + 2], acc[i][j + 3]);
            if (EPI >= 1) {
                v.x += bias[cidx];     v.y += bias[cidx + 1];
                v.z += bias[cidx + 2]; v.w += bias[cidx + 3];
            }
            if (EPI == 1) {
                v.x = fmaxf(v.x, 0.f); v.y = fmaxf(v.y, 0.f);
                v.z = fmaxf(v.z, 0.f); v.w = fmaxf(v.w, 0.f);
            }
            if (EPI == 2) {
                float4 rv = *reinterpret_cast<const float4*>(&res[(size_t)r * N + cidx]);
                v.x += rv.x; v.y += rv.y; v.z += rv.z; v.w += rv.w;
            }
            *reinterpret_cast<float4*>(&C[(size_t)r * N + cidx]) = v;
        }
    }
}

// ================= fused softmax + causal dynamic conv + LayerNorm =================
// one block per row m = t*B + b; 256 threads, 4 channels each
__global__ __launch_bounds__(256)
void dynconv_ln_kernel(const float* __restrict__ x, const float* __restrict__ wraw,
                       const float* __restrict__ b_lin,
                       const float* __restrict__ ln_g, const float* __restrict__ ln_b,
                       float* __restrict__ y) {
    const int m   = blockIdx.x;
    const int t   = m >> 3;            // B_DIM = 8
    const int tid = threadIdx.x;

    __shared__ float w_s[H_DIM * K_TAPS];   // 240
    __shared__ float redbuf[16];
    __shared__ float stats[2];

    if (tid < H_DIM * K_TAPS)
        w_s[tid] = wraw[m * NPAD + tid] + b_lin[tid];
    __syncthreads();

    // per-head softmax over K taps (16 heads, one thread each)
    if (tid < H_DIM) {
        float mx = -1e30f;
        #pragma unroll
        for (int k = 0; k < K_TAPS; k++) mx = fmaxf(mx, w_s[tid * K_TAPS + k]);
        float e[K_TAPS];
        float s = 0.f;
        #pragma unroll
        for (int k = 0; k < K_TAPS; k++) { e[k] = expf(w_s[tid * K_TAPS + k] - mx); s += e[k]; }
        const float inv = 1.0f / s;
        #pragma unroll
        for (int k = 0; k < K_TAPS; k++) w_s[tid * K_TAPS + k] = e[k] * inv;
    }
    __syncthreads();

    // causal conv: o[c] = sum_k w[h,k] * x[t + k - (K-1), b, c]
    const int kmin = (t >= K_TAPS - 1) ? 0 : (K_TAPS - 1 - t);
    float o[4];
    float sum = 0.f, sumsq = 0.f;
    #pragma unroll
    for (int i = 0; i < 4; i++) {
        const int c = tid + i * 256;
        const int h = c >> 6;             // R = 64 channels/head
        float a = 0.f;
        for (int k = kmin; k < K_TAPS; k++) {
            a += w_s[h * K_TAPS + k] *
                 x[(size_t)(m + (k - (K_TAPS - 1)) * B_DIM) * C_DIM + c];
        }
        o[i] = a;
        sum += a;
        sumsq += a * a;
    }

    // block reduction for mean / var
    float s1 = sum, s2 = sumsq;
    #pragma unroll
    for (int off = 16; off > 0; off >>= 1) {
        s1 += __shfl_down_sync(0xFFFFFFFFu, s1, off);
        s2 += __shfl_down_sync(0xFFFFFFFFu, s2, off);
    }
    const int wid  = tid >> 5;
    const int lane = tid & 31;
    if (lane == 0) { redbuf[wid] = s1; redbuf[8 + wid] = s2; }
    __syncthreads();
    if (tid == 0) {
        float a = 0.f, b = 0.f;
        #pragma unroll
        for (int i = 0; i < 8; i++) { a += redbuf[i]; b += redbuf[8 + i]; }
        const float mu  = a * (1.0f / C_DIM);
        const float var = b * (1.0f / C_DIM) - mu * mu;
        stats[0] = mu;
        stats[1] = rsqrtf(var + LN_EPS);
    }
    __syncthreads();
    const float mu = stats[0], rstd = stats[1];

    #pragma unroll
    for (int i = 0; i < 4; i++) {
        const int c = tid + i * 256;
        y[(size_t)m * C_DIM + c] = (o[i] - mu) * rstd * ln_g[c] + ln_b[c];
    }
}

// ================= launch =================
extern "C" void kernel_launch(void* const* d_in, const int* in_sizes, int n_in,
                              void* d_out, int out_size) {
    const float* x     = (const float*)d_in[0];
    const float* w_lin = (const float*)d_in[1];
    const float* b_lin = (const float*)d_in[2];
    const float* ln_g  = (const float*)d_in[3];
    const float* ln_b  = (const float*)d_in[4];
    const float* fc1_w = (const float*)d_in[5];
    const float* fc1_b = (const float*)d_in[6];
    const float* fc2_w = (const float*)d_in[7];
    const float* fc2_b = (const float*)d_in[8];
    float* out = (float*)d_out;

    float *wpad, *wraw, *y, *h;
    cudaGetSymbolAddress((void**)&wpad, g_wpad);
    cudaGetSymbolAddress((void**)&wraw, g_wraw);
    cudaGetSymbolAddress((void**)&y,    g_y);
    cudaGetSymbolAddress((void**)&h,    g_h);

    // 1) pad w_lin to 256 cols
    pad_wlin_kernel<<<(C_DIM * NPAD) / 256, 256>>>(w_lin, wpad);

    // 2) conv-weight projection: wraw = x @ wpad   (8192 x 256 x 1024)
    sgemm_kernel<0><<<dim3(NPAD / BN, M_DIM / BM), 256>>>(
        M_DIM, NPAD, C_DIM, x, wpad, nullptr, nullptr, wraw);

    // 3) softmax + causal dynamic conv + LayerNorm -> y
    dynconv_ln_kernel<<<M_DIM, 256>>>(x, wraw, b_lin, ln_g, ln_b, y);

    // 4) fc1 + ReLU: h = relu(y @ fc1_w + fc1_b)   (8192 x 4096 x 1024)
    sgemm_kernel<1><<<dim3(F_DIM / BN, M_DIM / BM), 256>>>(
        M_DIM, F_DIM, C_DIM, y, fc1_w, fc1_b, nullptr, h);

    // 5) fc2 + bias + residual(y): out = h @ fc2_w + fc2_b + y   (8192 x 1024 x 4096)
    sgemm_kernel<2><<<dim3(C_DIM / BN, M_DIM / BM), 256>>>(
        M_DIM, C_DIM, F_DIM, h, fc2_w, fc2_b, y, out);
}

// round 3
// speedup vs baseline: 8.7094x; 8.7094x over previous
#include <cuda_runtime.h>
#include <cuda.h>
#include <dlfcn.h>
#include <math.h>
#include <stdint.h>

// ---------------- problem constants ----------------
#define T_DIM 1024
#define B_DIM 8
#define C_DIM 1024
#define F_DIM 4096
#define H_DIM 16
#define K_TAPS 15
#define M_DIM (T_DIM * B_DIM)   // 8192
#define NPAD 256
#define LN_EPS 1e-5f

// tcgen05 GEMM tile config
#define BM 128
#define BN 256
#define BK 32                            // floats per k-chunk (128 bytes)
#define CHUNK_A_BYTES (BM * BK * 4)      // 16384
#define CHUNK_B_BYTES (BN * BK * 4)      // 32768
#define CHUNK_BYTES (CHUNK_A_BYTES + CHUNK_B_BYTES)
#define SMEM_BYTES (1024 + 1024 + 2 * CHUNK_BYTES)

// arch-specific feature gate (tcgen05 only exists on the sm_103a pass)
#if defined(__CUDA_ARCH_FEAT_SM103_ALL) || defined(__CUDA_ARCH_FEAT_SM100_ALL) || \
    (defined(__CUDA_ARCH_SPECIFIC__) && (__CUDA_ARCH_SPECIFIC__ >= 1000)) ||      \
    (defined(__CUDA_ARCH_FAMILY_SPECIFIC__) && (__CUDA_ARCH_FAMILY_SPECIFIC__ >= 1000))
#define TC_OK 1
#else
#define TC_OK 0
#endif

// ---------------- scratch (device globals) ----------------
__device__ int   g_use_tc;                              // 1 if tcgen05 cubin active
__device__ float g_wlinT[NPAD * C_DIM];                 // [256,1024] tf32-rounded
__device__ float g_fc1wT[(size_t)F_DIM * C_DIM];        // [4096,1024] tf32-rounded
__device__ float g_fc2wT[(size_t)C_DIM * F_DIM];        // [1024,4096] tf32-rounded
__device__ float g_wpad[C_DIM * NPAD];                  // fallback padded w_lin
__device__ float g_wraw[(size_t)M_DIM * NPAD];          // conv logits
__device__ float g_y[(size_t)M_DIM * C_DIM];            // post-LN (exact fp32)
__device__ float g_yrn[(size_t)M_DIM * C_DIM];          // post-LN (tf32-rounded)
__device__ float g_h[(size_t)M_DIM * F_DIM];            // fc1 output

// ---------------- generic helpers ----------------
__device__ __forceinline__ float to_tf32(float x) {
    float r;
    asm("cvt.rna.tf32.f32 %0, %1;" : "=f"(r) : "f"(x));
    return r;
}

__global__ void probe_kernel() {
#if TC_OK
    g_use_tc = 1;
#else
    g_use_tc = 0;
#endif
}

// ---------------- tcgen05-only helpers + kernel ----------------
__device__ __forceinline__ uint32_t smem_u32(const void* p) {
    uint32_t a;
    asm("{ .reg .u64 t; cvta.to.shared.u64 t, %1; cvt.u32.u64 %0, t; }" : "=r"(a) : "l"(p));
    return a;
}
__device__ __forceinline__ uint32_t elect_one() {
    uint32_t p;
    asm volatile("{ .reg .pred p; elect.sync _|p, 0xFFFFFFFF; selp.b32 %0, 1, 0, p; }" : "=r"(p));
    return p;
}
__device__ __forceinline__ void mbar_init(uint32_t a, uint32_t cnt) {
    asm volatile("mbarrier.init.shared.b64 [%0], %1;" :: "r"(a), "r"(cnt) : "memory");
}
__device__ __forceinline__ void mbar_expect_tx(uint32_t a, uint32_t bytes) {
    asm volatile("mbarrier.arrive.expect_tx.shared.b64 _, [%0], %1;" :: "r"(a), "r"(bytes) : "memory");
}
__device__ __forceinline__ void mbar_wait(uint32_t a, uint32_t parity) {
    uint32_t done;
    asm volatile(
        "{ .reg .pred p;\n\t"
        "mbarrier.try_wait.parity.acquire.cta.shared::cta.b64 p, [%1], %2;\n\t"
        "selp.b32 %0, 1, 0, p; }" : "=r"(done) : "r"(a), "r"(parity) : "memory");
    if (!done) {
        asm volatile(
            "{ .reg .pred P1;\n\t"
            "WL_%=:\n\t"
            "mbarrier.try_wait.parity.acquire.cta.shared::cta.b64 P1, [%0], %1, 0x989680;\n\t"
            "@P1 bra.uni WD_%=;\n\t"
            "bra.uni WL_%=;\n\t"
            "WD_%=: }" :: "r"(a), "r"(parity) : "memory");
    }
}
#if TC_OK
__device__ __forceinline__ void tma_2d(uint32_t dst, const void* map, int cx, int cy, uint32_t mbar) {
    asm volatile(
        "cp.async.bulk.tensor.2d.shared::cta.global.tile.mbarrier::complete_tx::bytes "
        "[%0], [%1, {%2, %3}], [%4];"
        :: "r"(dst), "l"(map), "r"(cx), "r"(cy), "r"(mbar) : "memory");
}
__device__ __forceinline__ void mma_tf32_ss(uint32_t d, uint64_t adesc, uint64_t bdesc,
                                            uint32_t idesc, uint32_t en) {
    asm volatile(
        "{ .reg .pred p;\n\t"
        "setp.ne.u32 p, %4, 0;\n\t"
        "tcgen05.mma.cta_group::1.kind::tf32 [%0], %1, %2, %3, p; }"
        :: "r"(d), "l"(adesc), "l"(bdesc), "r"(idesc), "r"(en) : "memory");
}
__device__ __forceinline__ void tc_commit(uint32_t mbar) {
    asm volatile(
        "tcgen05.commit.cta_group::1.mbarrier::arrive::one.shared::cluster.b64 [%0];"
        :: "r"(mbar) : "memory");
}
#define TC_ALLOC(smem_addr, ncols) \
    asm volatile("tcgen05.alloc.cta_group::1.sync.aligned.shared::cta.b32 [%0], %1;" \
                 :: "r"(smem_addr), "r"(ncols) : "memory")
#define TC_RELINQ() \
    asm volatile("tcgen05.relinquish_alloc_permit.cta_group::1.sync.aligned;")
#define TC_DEALLOC(tmem, ncols) \
    asm volatile("tcgen05.dealloc.cta_group::1.sync.aligned.b32 %0, %1;" :: "r"(tmem), "r"(ncols))
#define TC_FENCE_AFTER()  asm volatile("tcgen05.fence::after_thread_sync;" ::: "memory")
#define TC_WAIT_LD()      asm volatile("tcgen05.wait::ld.sync.aligned;" ::: "memory")
#define TC_LD_X32(r, addr) \
    asm volatile("tcgen05.ld.sync.aligned.32x32b.x32.b32 " \
        "{%0, %1, %2, %3, %4, %5, %6, %7, %8, %9, %10, %11, %12, %13, %14, %15, " \
        " %16, %17, %18, %19, %20, %21, %22, %23, %24, %25, %26, %27, %28, %29, %30, %31}, [%32];" \
        : "=r"((r)[0]), "=r"((r)[1]), "=r"((r)[2]), "=r"((r)[3]), \
          "=r"((r)[4]), "=r"((r)[5]), "=r"((r)[6]), "=r"((r)[7]), \
          "=r"((r)[8]), "=r"((r)[9]), "=r"((r)[10]), "=r"((r)[11]), \
          "=r"((r)[12]), "=r"((r)[13]), "=r"((r)[14]), "=r"((r)[15]), \
          "=r"((r)[16]), "=r"((r)[17]), "=r"((r)[18]), "=r"((r)[19]), \
          "=r"((r)[20]), "=r"((r)[21]), "=r"((r)[22]), "=r"((r)[23]), \
          "=r"((r)[24]), "=r"((r)[25]), "=r"((r)[26]), "=r"((r)[27]), \
          "=r"((r)[28]), "=r"((r)[29]), "=r"((r)[30]), "=r"((r)[31]) \
        : "r"(addr))

__device__ __forceinline__ uint64_t smem_desc_sw128(uint32_t addr) {
    return ((uint64_t)2 << 61) | ((uint64_t)1 << 46) | ((uint64_t)64 << 32) |
           ((uint64_t)1 << 16) | (((uint64_t)addr >> 4) & 0x3FFF);
}
#define IDESC_TF32 ((1u << 4) | (2u << 7) | (2u << 10) | ((BN / 8) << 17) | ((BM / 16) << 24))
#endif  // TC_OK

// tcgen05 tf32 GEMM: C[M,N] = A[M,K] @ Bt[N,K]^T, tile 128x256, double-buffered TMA.
// EPI: 0 plain, 1 bias+relu+tf32-round, 2 bias+residual
template <int EPI>
__global__ __launch_bounds__(128)
void tc_gemm(const __grid_constant__ CUtensorMap tmA,
             const __grid_constant__ CUtensorMap tmB,
             const float* __restrict__ bias, const float* __restrict__ res,
             float* __restrict__ C, int N, int NC) {
#if TC_OK
    extern __shared__ __align__(1024) char smem[];
    const int tid = threadIdx.x;
    const int warp = tid >> 5;
    const int lane = tid & 31;

    uint32_t sb = (smem_u32(smem) + 1023u) & ~1023u;
    const uint32_t tmem_ptr_addr = sb;
    const uint32_t mb_full[2] = { sb + 8, sb + 16 };
    const uint32_t mb_done[2] = { sb + 24, sb + 32 };
    const uint32_t bufA[2] = { sb + 1024, sb + 1024 + CHUNK_BYTES };
    const uint32_t bufB[2] = { sb + 1024 + CHUNK_A_BYTES, sb + 1024 + CHUNK_BYTES + CHUNK_A_BYTES };

    if (warp == 0) {
        TC_ALLOC(tmem_ptr_addr, BN);
        TC_RELINQ();
    }
    if (tid == 0) {
        mbar_init(mb_full[0], 1); mbar_init(mb_full[1], 1);
        mbar_init(mb_done[0], 1); mbar_init(mb_done[1], 1);
    }
    __syncthreads();

    uint32_t tmem;
    asm volatile("ld.shared.b32 %0, [%1];" : "=r"(tmem) : "r"(tmem_ptr_addr));

    const int tile_m = blockIdx.y * BM;
    const int tile_n = blockIdx.x * BN;

    if (warp == 0 && elect_one()) {
        const uint64_t ad[2] = { smem_desc_sw128(bufA[0]), smem_desc_sw128(bufA[1]) };
        const uint64_t bd[2] = { smem_desc_sw128(bufB[0]), smem_desc_sw128(bufB[1]) };
        int phf[2] = {0, 0}, phd[2] = {0, 0};

        mbar_expect_tx(mb_full[0], CHUNK_BYTES);
        tma_2d(bufA[0], &tmA, 0, tile_m, mb_full[0]);
        tma_2d(bufB[0], &tmB, 0, tile_n, mb_full[0]);
        if (NC > 1) {
            mbar_expect_tx(mb_full[1], CHUNK_BYTES);
            tma_2d(bufA[1], &tmA, BK, tile_m, mb_full[1]);
            tma_2d(bufB[1], &tmB, BK, tile_n, mb_full[1]);
        }

        for (int kc = 0; kc < NC; kc++) {
            const int b = kc & 1;
            mbar_wait(mb_full[b], phf[b]); phf[b] ^= 1;
            #pragma unroll
            for (int s = 0; s < 4; s++)    // BK=32 floats = 4 x (K=8) tf32 MMAs
                mma_tf32_ss(tmem, ad[b] + 2 * s, bd[b] + 2 * s, IDESC_TF32,
                            (kc > 0 || s > 0) ? 1u : 0u);
            tc_commit(mb_done[b]);
            if (kc + 2 < NC) {
                mbar_wait(mb_done[b], phd[b]); phd[b] ^= 1;
                mbar_expect_tx(mb_full[b], CHUNK_BYTES);
                tma_2d(bufA[b], &tmA, (kc + 2) * BK, tile_m, mb_full[b]);
                tma_2d(bufB[b], &tmB, (kc + 2) * BK, tile_n, mb_full[b]);
            }
        }
        const int bl = (NC - 1) & 1;
        mbar_wait(mb_done[bl], phd[bl]);
    }
    __syncthreads();
    TC_FENCE_AFTER();

    const int row = tile_m + warp * 32 + lane;
    #pragma unroll 1
    for (int cc = 0; cc < BN / 32; cc++) {
        uint32_t r[32];
        TC_LD_X32(r, tmem + cc * 32);
        TC_WAIT_LD();
        const int colbase = tile_n + cc * 32;
        float4* dst = reinterpret_cast<float4*>(&C[(size_t)row * N + colbase]);
        #pragma unroll
        for (int j = 0; j < 32; j += 4) {
            float4 v;
            v.x = __uint_as_float(r[j + 0]);
            v.y = __uint_as_float(r[j + 1]);
            v.z = __uint_as_float(r[j + 2]);
            v.w = __uint_as_float(r[j + 3]);
            if (EPI >= 1) {
                v.x += bias[colbase + j + 0]; v.y += bias[colbase + j + 1];
                v.z += bias[colbase + j + 2]; v.w += bias[colbase + j + 3];
            }
            if (EPI == 1) {
                v.x = to_tf32(fmaxf(v.x, 0.f)); v.y = to_tf32(fmaxf(v.y, 0.f));
                v.z = to_tf32(fmaxf(v.z, 0.f)); v.w = to_tf32(fmaxf(v.w, 0.f));
            }
            if (EPI == 2) {
                float4 rv = *reinterpret_cast<const float4*>(&res[(size_t)row * N + colbase + j]);
                v.x += rv.x; v.y += rv.y; v.z += rv.z; v.w += rv.w;
            }
            dst[j / 4] = v;
        }
    }
    __syncthreads();
    if (warp == 0) TC_DEALLOC(tmem, BN);
#endif  // TC_OK
}

// ================= fallback SIMT SGEMM (Round-1 proven; skipped when tcgen05 active) =================
constexpr int FBM = 128, FBN = 128, FBK = 16, FTM = 8, FTN = 8;

template <int EPI>
__global__ __launch_bounds__(256)
void sgemm_fallback(int M, int N, int Kd,
                    const float* __restrict__ A, const float* __restrict__ B,
                    const float* __restrict__ bias, const float* __restrict__ res,
                    float* __restrict__ C) {
    if (g_use_tc) return;
    __shared__ float As[FBK * FBM];
    __shared__ float Bs[FBK * FBN];

    const int cRow = blockIdx.y, cCol = blockIdx.x, tid = threadIdx.x;
    const int threadCol = tid % (FBN / FTN);
    const int threadRow = tid / (FBN / FTN);

    A += (size_t)cRow * FBM * Kd;
    B += (size_t)cCol * FBN;

    const int innerRowA = tid / (FBK / 4), innerColA = tid % (FBK / 4);
    const int innerRowB = tid / (FBN / 4), innerColB = tid % (FBN / 4);

    float acc[FTM][FTN] = {};
    float regM[FTM], regN[FTN];

    for (int k0 = 0; k0 < Kd; k0 += FBK) {
        #pragma unroll
        for (int p = 0; p < FBM; p += 64) {
            float4 v = *reinterpret_cast<const float4*>(
                &A[(size_t)(innerRowA + p) * Kd + innerColA * 4]);
            As[(innerColA * 4 + 0) * FBM + innerRowA + p] = v.x;
            As[(innerColA * 4 + 1) * FBM + innerRowA + p] = v.y;
            As[(innerColA * 4 + 2) * FBM + innerRowA + p] = v.z;
            As[(innerColA * 4 + 3) * FBM + innerRowA + p] = v.w;
        }
        #pragma unroll
        for (int p = 0; p < FBK; p += 8)
            *reinterpret_cast<float4*>(&Bs[(innerRowB + p) * FBN + innerColB * 4]) =
                *reinterpret_cast<const float4*>(&B[(size_t)(innerRowB + p) * N + innerColB * 4]);
        __syncthreads();
        A += FBK;
        B += (size_t)FBK * N;

        #pragma unroll
        for (int k = 0; k < FBK; k++) {
            #pragma unroll
            for (int i = 0; i < FTM; i++) regM[i] = As[k * FBM + threadRow * FTM + i];
            #pragma unroll
            for (int j = 0; j < FTN; j++) regN[j] = Bs[k * FBN + threadCol * FTN + j];
            #pragma unroll
            for (int i = 0; i < FTM; i++)
                #pragma unroll
                for (int j = 0; j < FTN; j++)
                    acc[i][j] += regM[i] * regN[j];
        }
        __syncthreads();
    }

    const int rowBase = cRow * FBM + threadRow * FTM;
    const int colBase = cCol * FBN + threadCol * FTN;
    #pragma unroll
    for (int i = 0; i < FTM; i++) {
        const int r = rowBase + i;
        #pragma unroll
        for (int j = 0; j < FTN; j += 4) {
            const int cidx = colBase + j;
            float4 v = make_float4(acc[i][j], acc[i][j + 1], acc[i][j + 2], acc[i][j + 3]);
            if (EPI >= 1) {
                v.x += bias[cidx];     v.y += bias[cidx + 1];
                v.z += bias[cidx + 2]; v.w += bias[cidx + 3];
            }
            if (EPI == 1) {
                v.x = fmaxf(v.x, 0.f); v.y = fmaxf(v.y, 0.f);
                v.z = fmaxf(v.z, 0.f); v.w = fmaxf(v.w, 0.f);
            }
            if (EPI == 2) {
                float4 rv = *reinterpret_cast<const float4*>(&res[(size_t)r * N + cidx]);
                v.x += rv.x; v.y += rv.y; v.z += rv.z; v.w += rv.w;
            }
            *reinterpret_cast<float4*>(&C[(size_t)r * N + cidx]) = v;
        }
    }
}

// ================= pad w_lin for fallback GEMM1 =================
__global__ void pad_wlin_kernel(const float* __restrict__ wlin, float* __restrict__ out) {
    int i = blockIdx.x * blockDim.x + threadIdx.x;
    int c = i >> 8, j = i & 255;
    out[i] = (j < H_DIM * K_TAPS) ? wlin[c * (H_DIM * K_TAPS) + j] : 0.0f;
}

// ================= transpose (+pad rows, +tf32 round) =================
__global__ void transpose_rn_kernel(const float* __restrict__ in, float* __restrict__ out,
                                    int R, int Cc, int Cp) {
    __shared__ float tile[32][33];
    const int c0 = blockIdx.x * 32, r0 = blockIdx.y * 32;
    const int x = c0 + threadIdx.x;
    #pragma unroll
    for (int i = 0; i < 32; i += 8) {
        const int y = r0 + threadIdx.y + i;
        float v = 0.f;
        if (x < Cc && y < R) v = in[(size_t)y * Cc + x];
        tile[threadIdx.y + i][threadIdx.x] = v;
    }
    __syncthreads();
    const int ox = r0 + threadIdx.x;
    #pragma unroll
    for (int i = 0; i < 32; i += 8) {
        const int oy = c0 + threadIdx.y + i;
        if (oy < Cp && ox < R)
            out[(size_t)oy * R + ox] = to_tf32(tile[threadIdx.x][threadIdx.y + i]);
    }
}

// ================= fused softmax + causal dynamic conv + LayerNorm =================
__global__ __launch_bounds__(256)
void dynconv_ln_kernel(const float* __restrict__ x, const float* __restrict__ wraw,
                       const float* __restrict__ b_lin,
                       const float* __restrict__ ln_g, const float* __restrict__ ln_b,
                       float* __restrict__ y, float* __restrict__ yrn) {
    const int m = blockIdx.x;
    const int t = m >> 3;
    const int tid = threadIdx.x;

    __shared__ float w_s[H_DIM * K_TAPS];
    __shared__ float redbuf[16];
    __shared__ float stats[2];

    if (tid < H_DIM * K_TAPS)
        w_s[tid] = wraw[(size_t)m * NPAD + tid] + b_lin[tid];
    __syncthreads();

    if (tid < H_DIM) {
        float mx = -1e30f;
        #pragma unroll
        for (int k = 0; k < K_TAPS; k++) mx = fmaxf(mx, w_s[tid * K_TAPS + k]);
        float e[K_TAPS]; float s = 0.f;
        #pragma unroll
        for (int k = 0; k < K_TAPS; k++) { e[k] = expf(w_s[tid * K_TAPS + k] - mx); s += e[k]; }
        const float inv = 1.0f / s;
        #pragma unroll
        for (int k = 0; k < K_TAPS; k++) w_s[tid * K_TAPS + k] = e[k] * inv;
    }
    __syncthreads();

    const int kmin = (t >= K_TAPS - 1) ? 0 : (K_TAPS - 1 - t);
    float o[4], sum = 0.f, sumsq = 0.f;
    #pragma unroll
    for (int i = 0; i < 4; i++) {
        const int c = tid + i * 256;
        const int h = c >> 6;
        float a = 0.f;
        for (int k = kmin; k < K_TAPS; k++)
            a += w_s[h * K_TAPS + k] * x[(size_t)(m + (k - (K_TAPS - 1)) * B_DIM) * C_DIM + c];
        o[i] = a; sum += a; sumsq += a * a;
    }

    float s1 = sum, s2 = sumsq;
    #pragma unroll
    for (int off = 16; off > 0; off >>= 1) {
        s1 += __shfl_down_sync(0xFFFFFFFFu, s1, off);
        s2 += __shfl_down_sync(0xFFFFFFFFu, s2, off);
    }
    const int wid = tid >> 5, lane = tid & 31;
    if (lane == 0) { redbuf[wid] = s1; redbuf[8 + wid] = s2; }
    __syncthreads();
    if (tid == 0) {
        float a = 0.f, b = 0.f;
        #pragma unroll
        for (int i = 0; i < 8; i++) { a += redbuf[i]; b += redbuf[8 + i]; }
        const float mu = a * (1.0f / C_DIM);
        const float var = b * (1.0f / C_DIM) - mu * mu;
        stats[0] = mu; stats[1] = rsqrtf(var + LN_EPS);
    }
    __syncthreads();
    const float mu = stats[0], rstd = stats[1];

    #pragma unroll
    for (int i = 0; i < 4; i++) {
        const int c = tid + i * 256;
        const float val = (o[i] - mu) * rstd * ln_g[c] + ln_b[c];
        y[(size_t)m * C_DIM + c] = val;
        yrn[(size_t)m * C_DIM + c] = to_tf32(val);
    }
}

// ================= host side =================
typedef CUresult (*PFN_encodeTiled)(CUtensorMap*, CUtensorMapDataType, cuuint32_t, void*,
                                    const cuuint64_t*, const cuuint64_t*, const cuuint32_t*,
                                    const cuuint32_t*, CUtensorMapInterleave, CUtensorMapSwizzle,
                                    CUtensorMapL2promotion, CUtensorMapFloatOOBfill);

static PFN_encodeTiled get_encoder() {
    static PFN_encodeTiled fn = nullptr;
    if (!fn) {
        void* h = dlopen("libcuda.so.1", RTLD_LAZY | RTLD_GLOBAL);
        if (!h) h = dlopen("libcuda.so", RTLD_LAZY | RTLD_GLOBAL);
        if (h) fn = (PFN_encodeTiled)dlsym(h, "cuTensorMapEncodeTiled");
    }
    return fn;
}

static void make_map(CUtensorMap* m, const void* ptr, uint64_t d0, uint64_t d1,
                     uint32_t b0, uint32_t b1) {
    cuuint64_t dims[2] = { d0, d1 };
    cuuint64_t strides[1] = { d0 * 4 };
    cuuint32_t box[2] = { b0, b1 };
    cuuint32_t es[2] = { 1, 1 };
    PFN_encodeTiled enc = get_encoder();
    if (enc)
        enc(m, CU_TENSOR_MAP_DATA_TYPE_FLOAT32, 2, (void*)ptr, dims, strides, box, es,
            CU_TENSOR_MAP_INTERLEAVE_NONE, CU_TENSOR_MAP_SWIZZLE_128B,
            CU_TENSOR_MAP_L2_PROMOTION_L2_128B, CU_TENSOR_MAP_FLOAT_OOB_FILL_NONE);
}

extern "C" void kernel_launch(void* const* d_in, const int* in_sizes, int n_in,
                              void* d_out, int out_size) {
    const float* x     = (const float*)d_in[0];
    const float* w_lin = (const float*)d_in[1];
    const float* b_lin = (const float*)d_in[2];
    const float* ln_g  = (const float*)d_in[3];
    const float* ln_b  = (const float*)d_in[4];
    const float* fc1_w = (const float*)d_in[5];
    const float* fc1_b = (const float*)d_in[6];
    const float* fc2_w = (const float*)d_in[7];
    const float* fc2_b = (const float*)d_in[8];
    float* out = (float*)d_out;

    float *wlinT, *fc1wT, *fc2wT, *wpad, *wraw, *y, *yrn, *h;
    cudaGetSymbolAddress((void**)&wlinT, g_wlinT);
    cudaGetSymbolAddress((void**)&fc1wT, g_fc1wT);
    cudaGetSymbolAddress((void**)&fc2wT, g_fc2wT);
    cudaGetSymbolAddress((void**)&wpad, g_wpad);
    cudaGetSymbolAddress((void**)&wraw, g_wraw);
    cudaGetSymbolAddress((void**)&y, g_y);
    cudaGetSymbolAddress((void**)&yrn, g_yrn);
    cudaGetSymbolAddress((void**)&h, g_h);

    cudaFuncSetAttribute(tc_gemm<0>, cudaFuncAttributeMaxDynamicSharedMemorySize, SMEM_BYTES);
    cudaFuncSetAttribute(tc_gemm<1>, cudaFuncAttributeMaxDynamicSharedMemorySize, SMEM_BYTES);
    cudaFuncSetAttribute(tc_gemm<2>, cudaFuncAttributeMaxDynamicSharedMemorySize, SMEM_BYTES);

    CUtensorMap mA1{}, mB1{}, mA2{}, mB2{}, mA3{}, mB3{};
    make_map(&mA1, x,     C_DIM, M_DIM, BK, BM);
    make_map(&mB1, wlinT, C_DIM, NPAD,  BK, BN);
    make_map(&mA2, yrn,   C_DIM, M_DIM, BK, BM);
    make_map(&mB2, fc1wT, C_DIM, F_DIM, BK, BN);
    make_map(&mA3, h,     F_DIM, M_DIM, BK, BM);
    make_map(&mB3, fc2wT, F_DIM, C_DIM, BK, BN);

    // 0) arch probe (sets g_use_tc before any flag-dependent kernel)
    probe_kernel<<<1, 1>>>();

    dim3 tb(32, 8);
    // 1) transposed tf32-rounded weights (tc path) + padded w_lin (fallback path)
    transpose_rn_kernel<<<dim3(NPAD / 32, C_DIM / 32), tb>>>(w_lin, wlinT, C_DIM, H_DIM * K_TAPS, NPAD);
    transpose_rn_kernel<<<dim3(F_DIM / 32, C_DIM / 32), tb>>>(fc1_w, fc1wT, C_DIM, F_DIM, F_DIM);
    transpose_rn_kernel<<<dim3(C_DIM / 32, F_DIM / 32), tb>>>(fc2_w, fc2wT, F_DIM, C_DIM, C_DIM);
    pad_wlin_kernel<<<(C_DIM * NPAD) / 256, 256>>>(w_lin, wpad);

    // 2) conv-weight projection: wraw = x @ w_lin (N padded to 256)
    tc_gemm<0><<<dim3(NPAD / BN, M_DIM / BM), 128, SMEM_BYTES>>>(
        mA1, mB1, nullptr, nullptr, wraw, NPAD, C_DIM / BK);
    sgemm_fallback<0><<<dim3(NPAD / FBN, M_DIM / FBM), 256>>>(
        M_DIM, NPAD, C_DIM, x, wpad, nullptr, nullptr, wraw);

    // 3) softmax + causal conv + LayerNorm
    dynconv_ln_kernel<<<M_DIM, 256>>>(x, wraw, b_lin, ln_g, ln_b, y, yrn);

    // 4) fc1 + ReLU
    tc_gemm<1><<<dim3(F_DIM / BN, M_DIM / BM), 128, SMEM_BYTES>>>(
        mA2, mB2, fc1_b, nullptr, h, F_DIM, C_DIM / BK);
    sgemm_fallback<1><<<dim3(F_DIM / FBN, M_DIM / FBM), 256>>>(
        M_DIM, F_DIM, C_DIM, y, fc1_w, fc1_b, nullptr, h);

    // 5) fc2 + bias + residual
    tc_gemm<2><<<dim3(C_DIM / BN, M_DIM / BM), 128, SMEM_BYTES>>>(
        mA3, mB3, fc2_b, y, out, C_DIM, F_DIM / BK);
    sgemm_fallback<2><<<dim3(C_DIM / FBN, M_DIM / FBM), 256>>>(
        M_DIM, C_DIM, F_DIM, h, fc2_w, fc2_b, y, out);
}